// round 4
// baseline (speedup 1.0000x reference)
#include <cuda_runtime.h>
#include <cstdint>

// compressor_17454747091102: bitwise majority vote (>=5 of 8) over packed sign bits.
//
// Reference semantics: bit b of output word m is set iff, across the 8 voters,
// at least 5 of src[v][m] have bit b set (vote sum 8-2c < 0  <=>  c >= 5;
// c == 4 gives sign(0) = 0 -> bit clear).
//
// Bit-sliced carry-save adder over 8 words -> 4-bit per-bit count, then
// threshold: out = c8 | (c4 & (c2 | c1)).
//
// NOTE: the harness declares the output dtype as float32 (evidence: NaN
// rel_err from raw int bit patterns interpreted as floats in round 1).
// We therefore store float32(numeric value of the signed int32 packed word).

__device__ __forceinline__ void full_add(uint32_t a, uint32_t b, uint32_t c,
                                         uint32_t& s, uint32_t& cy) {
    uint32_t ab = a ^ b;
    s  = ab ^ c;
    cy = (a & b) | (c & ab);
}

__device__ __forceinline__ uint32_t maj5of8(const uint32_t w[8]) {
    uint32_t s_a, c_a, s_b, c_b, s_c, c_c;
    full_add(w[0], w[1], w[2], s_a, c_a);
    full_add(w[3], w[4], w[5], s_b, c_b);
    full_add(w[6], w[7], s_a, s_c, c_c);
    // weight-1 leftovers: s_b, s_c
    uint32_t s_d = s_b ^ s_c;          // weight-1 result bit (c1)
    uint32_t c_d = s_b & s_c;          // carry to weight-2
    // weight-2 inputs: c_a, c_b, c_c, c_d
    uint32_t s_e, c_e;
    full_add(c_a, c_b, c_c, s_e, c_e);
    uint32_t s_f = s_e ^ c_d;          // weight-2 result bit (c2)
    uint32_t c_f = s_e & c_d;          // carry to weight-4
    // weight-4 inputs: c_e, c_f
    uint32_t s_g = c_e ^ c_f;          // weight-4 result bit (c4)
    uint32_t c_g = c_e & c_f;          // weight-8 bit (c8), set iff count == 8
    // count >= 5  <=>  c8 | (c4 & (c2 | c1))
    return c_g | (s_g & (s_f | s_d));
}

__global__ void __launch_bounds__(256)
compressor_17454747091102_kernel(const uint4* __restrict__ src,
                                 float4* __restrict__ out, int m4) {
    int i = blockIdx.x * blockDim.x + threadIdx.x;
    if (i >= m4) return;

    uint4 v[8];
#pragma unroll
    for (int t = 0; t < 8; t++)
        v[t] = src[(size_t)t * m4 + i];

    uint32_t wx[8], wy[8], wz[8], ww[8];
#pragma unroll
    for (int t = 0; t < 8; t++) {
        wx[t] = v[t].x; wy[t] = v[t].y; wz[t] = v[t].z; ww[t] = v[t].w;
    }

    // Packed majority words, then convert their *signed int32 value* to float32.
    float4 r;
    r.x = (float)(int)maj5of8(wx);
    r.y = (float)(int)maj5of8(wy);
    r.z = (float)(int)maj5of8(wz);
    r.w = (float)(int)maj5of8(ww);
    out[i] = r;
}

extern "C" void kernel_launch(void* const* d_in, const int* in_sizes, int n_in,
                              void* d_out, int out_size) {
    // d_in[0] = para_temp (float, unused), d_in[1] = src_tensor_list (int32, 8*M)
    const uint4* src = (const uint4*)d_in[1];
    float4* out = (float4*)d_out;
    int M  = in_sizes[1] / 8;   // packed words per voter
    int m4 = M / 4;             // uint4 elements per voter (M = 2^20, divisible by 4)
    int threads = 256;
    int blocks = (m4 + threads - 1) / threads;
    compressor_17454747091102_kernel<<<blocks, threads>>>(src, out, m4);
}

// round 8
// speedup vs baseline: 1.4498x; 1.4498x over previous
#include <cuda_runtime.h>
#include <cstdint>

// compressor_17454747091102: bitwise majority vote (>=5 of 8) over packed sign bits.
// out bit set iff >=5 of 8 voters have the bit set (vote sum < 0).
// Bit-sliced carry-save adder -> threshold c8 | (c4 & (c2 | c1)).
// Output buffer dtype is float32 (round-1 evidence): store float32((int32)word).
//
// R4 ncu: DRAM 42%, issue 18%, 2-wave tail (1024 blocks @ 6 blocks/SM cap).
// R5 change: 2 tiles per thread (i and i+half) -> 512 blocks, single wave,
// software-pipelined by unroll. Both tiles fully coalesced.

__device__ __forceinline__ void full_add(uint32_t a, uint32_t b, uint32_t c,
                                         uint32_t& s, uint32_t& cy) {
    uint32_t ab = a ^ b;
    s  = ab ^ c;
    cy = (a & b) | (c & ab);
}

__device__ __forceinline__ uint32_t maj5of8(const uint32_t w[8]) {
    uint32_t s_a, c_a, s_b, c_b, s_c, c_c;
    full_add(w[0], w[1], w[2], s_a, c_a);
    full_add(w[3], w[4], w[5], s_b, c_b);
    full_add(w[6], w[7], s_a, s_c, c_c);
    uint32_t s_d = s_b ^ s_c;          // c1
    uint32_t c_d = s_b & s_c;
    uint32_t s_e, c_e;
    full_add(c_a, c_b, c_c, s_e, c_e);
    uint32_t s_f = s_e ^ c_d;          // c2
    uint32_t c_f = s_e & c_d;
    uint32_t s_g = c_e ^ c_f;          // c4
    uint32_t c_g = c_e & c_f;          // c8
    return c_g | (s_g & (s_f | s_d)); // count >= 5
}

__global__ void __launch_bounds__(256)
compressor_17454747091102_kernel(const uint4* __restrict__ src,
                                 float4* __restrict__ out,
                                 int m4, int half) {
    int i = blockIdx.x * blockDim.x + threadIdx.x;
    if (i >= half) return;

#pragma unroll
    for (int rep = 0; rep < 2; rep++) {
        int idx = i + rep * half;

        uint4 v[8];
#pragma unroll
        for (int t = 0; t < 8; t++)
            v[t] = src[(size_t)t * m4 + idx];

        uint32_t wx[8], wy[8], wz[8], ww[8];
#pragma unroll
        for (int t = 0; t < 8; t++) {
            wx[t] = v[t].x; wy[t] = v[t].y; wz[t] = v[t].z; ww[t] = v[t].w;
        }

        float4 r;
        r.x = (float)(int)maj5of8(wx);
        r.y = (float)(int)maj5of8(wy);
        r.z = (float)(int)maj5of8(wz);
        r.w = (float)(int)maj5of8(ww);
        out[idx] = r;
    }
}

extern "C" void kernel_launch(void* const* d_in, const int* in_sizes, int n_in,
                              void* d_out, int out_size) {
    // d_in[0] = para_temp (float, unused), d_in[1] = src_tensor_list (int32, 8*M)
    const uint4* src = (const uint4*)d_in[1];
    float4* out = (float4*)d_out;
    int M    = in_sizes[1] / 8;   // packed words per voter (2^20)
    int m4   = M / 4;             // uint4 tiles per voter (262144)
    int half = m4 / 2;            // tiles handled in first pass (131072)
    int threads = 256;
    int blocks = (half + threads - 1) / threads;   // 512
    compressor_17454747091102_kernel<<<blocks, threads>>>(src, out, m4, half);
}